// round 2
// baseline (speedup 1.0000x reference)
#include <cuda_runtime.h>
#include <cuda_bf16.h>
#include <cstddef>

// Problem constants
#define NROWS   32768      // 32*1024 flattened z rows
#define NCODES  1024
#define DIM     256

// ---------------- scratch (static device globals; no runtime alloc) ----------
__device__ float g_dist[(size_t)NROWS * NCODES];   // 128 MB distances
__device__ float g_se[NCODES];                     // sum(emb^2) per code (sequential order)
__device__ float g_sz[NROWS];                      // sum(z^2) per row (sequential order)
__device__ float g_colsum[NCODES];
__device__ float g_loss;
__device__ int   g_idx[NROWS];

// ---------------- kernel 1: se_k = sequential sum of fl(e^2); zero accums ----
// One thread per code; strict ascending-d order with square rounded first,
// mimicking XLA:CPU scalar reduce of (emb**2).
__global__ void prep_se_kernel(const float* __restrict__ E) {
    int code = blockIdx.x * blockDim.x + threadIdx.x;
    if (code < NCODES) {
        const float* e = E + (size_t)code * DIM;
        float s = 0.f;
        for (int i = 0; i < DIM; i += 4) {
            float4 v = *(const float4*)(e + i);
            s = __fadd_rn(s, __fmul_rn(v.x, v.x));
            s = __fadd_rn(s, __fmul_rn(v.y, v.y));
            s = __fadd_rn(s, __fmul_rn(v.z, v.z));
            s = __fadd_rn(s, __fmul_rn(v.w, v.w));
        }
        g_se[code] = s;
        g_colsum[code] = 0.f;
    }
    if (blockIdx.x == 0 && threadIdx.x == 0) g_loss = 0.f;
}

// ---------------- kernel 1b: sz_n = sequential sum of fl(z^2) ----------------
__global__ void prep_sz_kernel(const float* __restrict__ Z) {
    int row = blockIdx.x * blockDim.x + threadIdx.x;
    if (row >= NROWS) return;
    const float* z = Z + (size_t)row * DIM;
    float s = 0.f;
    for (int i = 0; i < DIM; i += 4) {
        float4 v = *(const float4*)(z + i);
        s = __fadd_rn(s, __fmul_rn(v.x, v.x));
        s = __fadd_rn(s, __fmul_rn(v.y, v.y));
        s = __fadd_rn(s, __fmul_rn(v.z, v.z));
        s = __fadd_rn(s, __fmul_rn(v.w, v.w));
    }
    g_sz[row] = s;
}

// ---------------- kernel 2: SGEMM  d = fl(fl(sz+se) - 2*dot) -----------------
// Block tile 128x128, K-chunk 16, 256 threads, 8x8 register tile per thread.
// Each output's dot is a strict ascending-k fused-FMA chain (Eigen gebp order).
#define BM 128
#define BN 128
#define BK 16
#define AS_STRIDE 136

__global__ __launch_bounds__(256) void gemm_dist_kernel(
    const float* __restrict__ Z, const float* __restrict__ E) {
    __shared__ __align__(16) float As[BK][AS_STRIDE];   // [d][m]
    __shared__ __align__(16) float Bs[BK][AS_STRIDE];   // [d][n]

    const int m0 = blockIdx.y * BM;
    const int n0 = blockIdx.x * BN;
    const int tid = threadIdx.x;
    const int tx = tid & 15;     // col group (8 cols)
    const int ty = tid >> 4;     // row group (8 rows)

    float acc[8][8];
    #pragma unroll
    for (int i = 0; i < 8; i++)
        #pragma unroll
        for (int j = 0; j < 8; j++) acc[i][j] = 0.f;

    const int lrow = tid >> 2;   // 0..63
    const int lc4  = tid & 3;    // 0..3

    for (int d0 = 0; d0 < DIM; d0 += BK) {
        #pragma unroll
        for (int r = 0; r < 2; r++) {
            int row = lrow + r * 64;
            float4 a = *(const float4*)(Z + (size_t)(m0 + row) * DIM + d0 + lc4 * 4);
            As[lc4 * 4 + 0][row] = a.x;
            As[lc4 * 4 + 1][row] = a.y;
            As[lc4 * 4 + 2][row] = a.z;
            As[lc4 * 4 + 3][row] = a.w;
            float4 b = *(const float4*)(E + (size_t)(n0 + row) * DIM + d0 + lc4 * 4);
            Bs[lc4 * 4 + 0][row] = b.x;
            Bs[lc4 * 4 + 1][row] = b.y;
            Bs[lc4 * 4 + 2][row] = b.z;
            Bs[lc4 * 4 + 3][row] = b.w;
        }
        __syncthreads();
        #pragma unroll
        for (int d = 0; d < BK; d++) {
            float af[8], bf[8];
            *(float4*)(af)     = *(const float4*)&As[d][ty * 8];
            *(float4*)(af + 4) = *(const float4*)&As[d][ty * 8 + 4];
            *(float4*)(bf)     = *(const float4*)&Bs[d][tx * 8];
            *(float4*)(bf + 4) = *(const float4*)&Bs[d][tx * 8 + 4];
            #pragma unroll
            for (int i = 0; i < 8; i++)
                #pragma unroll
                for (int j = 0; j < 8; j++)
                    acc[i][j] = __fmaf_rn(af[i], bf[j], acc[i][j]);
        }
        __syncthreads();
    }

    // epilogue: d = fl(fl(sz + se) - 2*dot)  (2*dot is exact)
    float sq[8];
    *(float4*)(sq)     = *(const float4*)(g_se + n0 + tx * 8);
    *(float4*)(sq + 4) = *(const float4*)(g_se + n0 + tx * 8 + 4);
    #pragma unroll
    for (int i = 0; i < 8; i++) {
        int row = m0 + ty * 8 + i;
        float szv = g_sz[row];
        float* dst = g_dist + (size_t)row * NCODES + n0 + tx * 8;
        float o[8];
        #pragma unroll
        for (int j = 0; j < 8; j++) {
            float t1 = __fadd_rn(szv, sq[j]);
            o[j] = __fadd_rn(t1, -(2.0f * acc[i][j]));
        }
        *(float4*)(dst)     = *(const float4*)(o);
        *(float4*)(dst + 4) = *(const float4*)(o + 4);
    }
}

// ---------------- kernel 3: row argmin + softmax stats + column sums ---------
// Block = 256 threads (8 warps); each warp processes 16 rows.
__global__ __launch_bounds__(256) void softmax_kernel(float* __restrict__ out_idx_f) {
    const int warp = threadIdx.x >> 5;
    const int lane = threadIdx.x & 31;
    const int row0 = blockIdx.x * 128 + warp * 16;

    float colacc[32];
    #pragma unroll
    for (int i = 0; i < 32; i++) colacc[i] = 0.f;

    for (int r = 0; r < 16; r++) {
        const int row = row0 + r;
        const float* D = g_dist + (size_t)row * NCODES;
        float v[32];
        #pragma unroll
        for (int i = 0; i < 32; i++) v[i] = D[i * 32 + lane];

        // argmin over distances, ties -> smallest global index (jnp.argmin)
        float m = v[0];
        int   mi = lane;                 // k = i*32 + lane
        #pragma unroll
        for (int i = 1; i < 32; i++) {
            int k = i * 32 + lane;
            if (v[i] < m) { m = v[i]; mi = k; }
        }
        #pragma unroll
        for (int o = 16; o; o >>= 1) {
            float om = __shfl_xor_sync(0xffffffffu, m, o);
            int   oi = __shfl_xor_sync(0xffffffffu, mi, o);
            if (om < m || (om == m && oi < mi)) { m = om; mi = oi; }
        }

        // softmax of x = -d/T with x - xmax ~= (dmin - d)*20
        float s = 0.f;
        #pragma unroll
        for (int i = 0; i < 32; i++) {
            v[i] = __expf((m - v[i]) * 20.0f);
            s += v[i];
        }
        #pragma unroll
        for (int o = 16; o; o >>= 1) s += __shfl_xor_sync(0xffffffffu, s, o);
        float inv = 1.0f / s;

        #pragma unroll
        for (int i = 0; i < 32; i++) colacc[i] = __fmaf_rn(v[i], inv, colacc[i]);

        if (lane == 0) {
            g_idx[row] = mi;
            out_idx_f[row] = (float)mi;
        }
    }
    #pragma unroll
    for (int i = 0; i < 32; i++)
        atomicAdd(&g_colsum[i * 32 + lane], colacc[i]);
}

// ---------------- kernel 4: gather quantized, straight-through, loss ---------
__global__ __launch_bounds__(256) void gather_loss_kernel(
    const float* __restrict__ Z, const float* __restrict__ E,
    float* __restrict__ out_q) {
    const int row = blockIdx.x;
    const int t = threadIdx.x;          // 256 threads == DIM
    const int idx = g_idx[row];
    float e  = E[(size_t)idx * DIM + t];
    float zv = Z[(size_t)row * DIM + t];
    // straight-through value: fl(z + fl(q - z)), same two roundings as JAX
    float diff = __fadd_rn(e, -zv);
    out_q[(size_t)row * DIM + t] = __fadd_rn(zv, diff);
    float sq = diff * diff;

    __shared__ float red[8];
    #pragma unroll
    for (int o = 16; o; o >>= 1) sq += __shfl_xor_sync(0xffffffffu, sq, o);
    if ((t & 31) == 0) red[t >> 5] = sq;
    __syncthreads();
    if (t < 8) {
        float x = red[t];
        #pragma unroll
        for (int o = 4; o; o >>= 1) x += __shfl_xor_sync(0xffu, x, o);
        if (t == 0) atomicAdd(&g_loss, x);
    }
}

// ---------------- kernel 5: finalize scalar loss + avg soft probs ------------
__global__ void finalize_kernel(float* __restrict__ out_loss,
                                float* __restrict__ out_avg) {
    int k = blockIdx.x * blockDim.x + threadIdx.x;
    if (k < NCODES) out_avg[k] = g_colsum[k] * (1.0f / (float)NROWS);  // /2^15 exact
    if (k == 0) {
        float mse = g_loss * (1.0f / (float)((size_t)NROWS * DIM));
        out_loss[0] = __fadd_rn(mse, 0.25f * mse);   // q_latent + 0.25*e_latent
    }
}

// ---------------------------------------------------------------------------
extern "C" void kernel_launch(void* const* d_in, const int* in_sizes, int n_in,
                              void* d_out, int out_size) {
    const float* Z = (const float*)d_in[0];
    const float* E = (const float*)d_in[1];
    if (n_in >= 2 && in_sizes[0] == NCODES * DIM && in_sizes[1] == NROWS * DIM) {
        E = (const float*)d_in[0];
        Z = (const float*)d_in[1];
    }

    float* out       = (float*)d_out;
    float* out_q     = out;                              // 8388608
    float* out_loss  = out + (size_t)NROWS * DIM;        // 1
    float* out_idx_f = out_loss + 1;                     // 32768
    float* out_avg   = out_idx_f + NROWS;                // 1024

    prep_se_kernel<<<(NCODES + 255) / 256, 256>>>(E);
    prep_sz_kernel<<<NROWS / 256, 256>>>(Z);
    dim3 grid(NCODES / BN, NROWS / BM);                  // (8, 256)
    gemm_dist_kernel<<<grid, 256>>>(Z, E);
    softmax_kernel<<<NROWS / 128, 256>>>(out_idx_f);
    gather_loss_kernel<<<NROWS, 256>>>(Z, E, out_q);
    finalize_kernel<<<(NCODES + 255) / 256, 256>>>(out_loss, out_avg);
}

// round 4
// speedup vs baseline: 1.5896x; 1.5896x over previous
#include <cuda_runtime.h>
#include <cuda_bf16.h>
#include <cstdint>
#include <cstddef>

// Problem constants
#define NROWS   32768
#define NCODES  1024
#define DIM     256
#define MARGIN  6e-3f
#define CAND_CAP (1 << 21)

// ---------------- scratch (static device globals) ---------------------------
__device__ float g_dist[(size_t)NROWS * NCODES];      // 128 MB approx distances
__device__ __nv_bfloat16 g_Zb[(size_t)NROWS * DIM];   // 16 MB
__device__ __nv_bfloat16 g_Eb[(size_t)NCODES * DIM];  // 0.5 MB
__device__ float g_se[NCODES];
__device__ float g_sz[NROWS];
__device__ float g_colsum[NCODES];
__device__ float g_loss;
__device__ unsigned long long g_key[NROWS];           // packed (dist_bits, code)
__device__ int   g_cand_count;
__device__ int   g_cand_row[CAND_CAP];
__device__ int   g_cand_code[CAND_CAP];

__device__ __forceinline__ uint32_t smem_u32(const void* p) {
    uint32_t a;
    asm("{ .reg .u64 t; cvta.to.shared.u64 t, %1; cvt.u32.u64 %0, t; }"
        : "=r"(a) : "l"(p));
    return a;
}

__device__ __forceinline__ uint32_t pack_bf2(float lo, float hi) {
    __nv_bfloat162 h = __floats2bfloat162_rn(lo, hi);
    return *(uint32_t*)&h;
}

// ---------------- kernel 1: se (exact chain) + E->bf16 + zero accums ---------
__global__ void prep_se_kernel(const float* __restrict__ E) {
    int code = blockIdx.x * blockDim.x + threadIdx.x;
    if (code < NCODES) {
        const float4* e4 = (const float4*)(E + (size_t)code * DIM);
        uint4* eb = (uint4*)(g_Eb + (size_t)code * DIM);
        float s = 0.f;
        for (int i = 0; i < 64; i += 2) {
            float4 a = e4[i], b = e4[i + 1];
            s = __fadd_rn(s, __fmul_rn(a.x, a.x));
            s = __fadd_rn(s, __fmul_rn(a.y, a.y));
            s = __fadd_rn(s, __fmul_rn(a.z, a.z));
            s = __fadd_rn(s, __fmul_rn(a.w, a.w));
            s = __fadd_rn(s, __fmul_rn(b.x, b.x));
            s = __fadd_rn(s, __fmul_rn(b.y, b.y));
            s = __fadd_rn(s, __fmul_rn(b.z, b.z));
            s = __fadd_rn(s, __fmul_rn(b.w, b.w));
            uint4 o;
            o.x = pack_bf2(a.x, a.y); o.y = pack_bf2(a.z, a.w);
            o.z = pack_bf2(b.x, b.y); o.w = pack_bf2(b.z, b.w);
            eb[i >> 1] = o;
        }
        g_se[code] = s;
        g_colsum[code] = 0.f;
    }
    if (blockIdx.x == 0 && threadIdx.x == 0) { g_loss = 0.f; g_cand_count = 0; }
}

// ---------------- kernel 1b: sz (exact chain) + Z->bf16 + key init -----------
__global__ void prep_sz_kernel(const float* __restrict__ Z) {
    int row = blockIdx.x * blockDim.x + threadIdx.x;
    if (row >= NROWS) return;
    const float4* z4 = (const float4*)(Z + (size_t)row * DIM);
    uint4* zb = (uint4*)(g_Zb + (size_t)row * DIM);
    float s = 0.f;
    for (int i = 0; i < 64; i += 2) {
        float4 a = z4[i], b = z4[i + 1];
        s = __fadd_rn(s, __fmul_rn(a.x, a.x));
        s = __fadd_rn(s, __fmul_rn(a.y, a.y));
        s = __fadd_rn(s, __fmul_rn(a.z, a.z));
        s = __fadd_rn(s, __fmul_rn(a.w, a.w));
        s = __fadd_rn(s, __fmul_rn(b.x, b.x));
        s = __fadd_rn(s, __fmul_rn(b.y, b.y));
        s = __fadd_rn(s, __fmul_rn(b.z, b.z));
        s = __fadd_rn(s, __fmul_rn(b.w, b.w));
        uint4 o;
        o.x = pack_bf2(a.x, a.y); o.y = pack_bf2(a.z, a.w);
        o.z = pack_bf2(b.x, b.y); o.w = pack_bf2(b.z, b.w);
        zb[i >> 1] = o;
    }
    g_sz[row] = s;
    g_key[row] = 0xFFFFFFFFFFFFFFFFull;
}

// ---------------- kernel 2: bf16 mma.sync GEMM -> approx distances -----------
// Block: 128(M) x 128(N) x K=256 in one pass. 256 threads = 8 warps (2x4 grid),
// warp tile 64x32 via m16n8k16. Smem tiles [128][264] bf16 (528B stride,
// conflict-free ldmatrix).
#define LDS_E 264
#define SM_SE   0                       // 128 floats
#define SM_SZ   512                     // 128 floats
#define SM_A    1024                    // 128*264*2 = 67584 B
#define SM_B    (1024 + 67584)
#define SM_TOT  (1024 + 2 * 67584)
#define STG_LD  132                     // staging stride in floats

__global__ __launch_bounds__(256) void gemm_mma_kernel() {
    extern __shared__ __align__(1024) char smem[];
    const int tid = threadIdx.x, wid = tid >> 5, lane = tid & 31;
    const int m0 = blockIdx.y * 128, n0 = blockIdx.x * 128;

    float* s_se = (float*)(smem + SM_SE);
    float* s_sz = (float*)(smem + SM_SZ);
    __nv_bfloat16* As = (__nv_bfloat16*)(smem + SM_A);
    __nv_bfloat16* Bs = (__nv_bfloat16*)(smem + SM_B);

    if (tid < 128) s_se[tid] = g_se[n0 + tid];
    else           s_sz[tid - 128] = g_sz[m0 + tid - 128];

    // Global -> smem tiles: thread handles half a row (128 bf16 = 16 uint4)
    {
        const int row = tid >> 1, half = tid & 1;
        const uint4* srcA = (const uint4*)(g_Zb + (size_t)(m0 + row) * DIM) + half * 16;
        const uint4* srcB = (const uint4*)(g_Eb + (size_t)(n0 + row) * DIM) + half * 16;
        uint4* dstA = (uint4*)(As + row * LDS_E + half * 128);
        uint4* dstB = (uint4*)(Bs + row * LDS_E + half * 128);
        #pragma unroll
        for (int i = 0; i < 16; i++) { dstA[i] = srcA[i]; dstB[i] = srcB[i]; }
    }
    __syncthreads();

    // Warp tiling: 2(M) x 4(N) warps; warp tile 64x32 = 4 m16 x 4 n8
    const int wm = (wid >> 2) * 64;
    const int wn = (wid & 3) * 32;

    float acc[4][4][4];
    #pragma unroll
    for (int i = 0; i < 4; i++)
        #pragma unroll
        for (int j = 0; j < 4; j++)
            #pragma unroll
            for (int e = 0; e < 4; e++) acc[i][j][e] = 0.f;

    const uint32_t a_base = smem_u32(As);
    const uint32_t b_base = smem_u32(Bs);
    const int a_row = wm + (lane & 15);
    const int a_kh  = (lane >> 4) << 3;
    const int b_row = wn + (lane & 7);
    const int b_kh  = ((lane >> 3) & 1) << 3;

    #pragma unroll
    for (int ks = 0; ks < 16; ks++) {
        const int k0 = ks * 16;
        uint32_t a[4][4], b[4][2];
        #pragma unroll
        for (int mt = 0; mt < 4; mt++) {
            uint32_t addr = a_base + ((a_row + mt * 16) * LDS_E + k0 + a_kh) * 2;
            asm volatile("ldmatrix.sync.aligned.m8n8.x4.shared.b16 {%0,%1,%2,%3}, [%4];"
                         : "=r"(a[mt][0]), "=r"(a[mt][1]), "=r"(a[mt][2]), "=r"(a[mt][3])
                         : "r"(addr));
        }
        #pragma unroll
        for (int nt = 0; nt < 4; nt++) {
            uint32_t addr = b_base + ((b_row + nt * 8) * LDS_E + k0 + b_kh) * 2;
            asm volatile("ldmatrix.sync.aligned.m8n8.x2.shared.b16 {%0,%1}, [%2];"
                         : "=r"(b[nt][0]), "=r"(b[nt][1]) : "r"(addr));
        }
        #pragma unroll
        for (int mt = 0; mt < 4; mt++)
            #pragma unroll
            for (int nt = 0; nt < 4; nt++) {
                asm volatile(
                    "mma.sync.aligned.m16n8k16.row.col.f32.bf16.bf16.f32 "
                    "{%0,%1,%2,%3}, {%4,%5,%6,%7}, {%8,%9}, {%0,%1,%2,%3};"
                    : "+f"(acc[mt][nt][0]), "+f"(acc[mt][nt][1]),
                      "+f"(acc[mt][nt][2]), "+f"(acc[mt][nt][3])
                    : "r"(a[mt][0]), "r"(a[mt][1]), "r"(a[mt][2]), "r"(a[mt][3]),
                      "r"(b[nt][0]), "r"(b[nt][1]));
            }
    }
    __syncthreads();   // all ldmatrix reads done; safe to reuse As as staging

    // Epilogue: d~ = fl(fl(sz+se) - 2*acc) into staging smem, then wide store.
    float* stage = (float*)(smem + SM_A);   // [128][132] floats
    {
        const int r0 = lane >> 2;
        const int c0 = (lane & 3) * 2;
        #pragma unroll
        for (int mt = 0; mt < 4; mt++) {
            const int mA = wm + mt * 16 + r0;
            const int mB = mA + 8;
            const float szA = s_sz[mA], szB = s_sz[mB];
            #pragma unroll
            for (int nt = 0; nt < 4; nt++) {
                const int n = wn + nt * 8 + c0;
                const float t0 = __fadd_rn(szA, s_se[n]);
                const float t1 = __fadd_rn(szA, s_se[n + 1]);
                const float t2 = __fadd_rn(szB, s_se[n]);
                const float t3 = __fadd_rn(szB, s_se[n + 1]);
                float2 vA, vB;
                vA.x = __fadd_rn(t0, -(2.0f * acc[mt][nt][0]));
                vA.y = __fadd_rn(t1, -(2.0f * acc[mt][nt][1]));
                vB.x = __fadd_rn(t2, -(2.0f * acc[mt][nt][2]));
                vB.y = __fadd_rn(t3, -(2.0f * acc[mt][nt][3]));
                *(float2*)&stage[mA * STG_LD + n] = vA;
                *(float2*)&stage[mB * STG_LD + n] = vB;
            }
        }
    }
    __syncthreads();
    #pragma unroll
    for (int it = 0; it < 16; it++) {
        const int r = it * 8 + wid;
        const int c = lane * 4;
        float4 val = *(float4*)&stage[r * STG_LD + c];
        *(float4*)(g_dist + (size_t)(m0 + r) * NCODES + n0 + c) = val;
    }
}

// ---------------- kernel 3: row min + candidates + softmax column sums -------
__global__ __launch_bounds__(256) void softmax_kernel() {
    const int warp = threadIdx.x >> 5;
    const int lane = threadIdx.x & 31;
    const int row0 = blockIdx.x * 128 + warp * 16;

    float colacc[32];
    #pragma unroll
    for (int i = 0; i < 32; i++) colacc[i] = 0.f;

    for (int r = 0; r < 16; r++) {
        const int row = row0 + r;
        const float* D = g_dist + (size_t)row * NCODES;
        float v[32];
        #pragma unroll
        for (int i = 0; i < 32; i++) v[i] = D[i * 32 + lane];

        float m = v[0];
        #pragma unroll
        for (int i = 1; i < 32; i++) m = fminf(m, v[i]);
        #pragma unroll
        for (int o = 16; o; o >>= 1) m = fminf(m, __shfl_xor_sync(0xffffffffu, m, o));

        // candidate append (exact-containment margin), warp-aggregated
        const float thr = m + MARGIN;
        int cl = 0;
        #pragma unroll
        for (int i = 0; i < 32; i++) cl += (v[i] <= thr);
        int pref = cl;
        #pragma unroll
        for (int o = 1; o < 32; o <<= 1) {
            int t = __shfl_up_sync(0xffffffffu, pref, o);
            if (lane >= o) pref += t;
        }
        int total = __shfl_sync(0xffffffffu, pref, 31);
        int base = 0;
        if (lane == 0) base = atomicAdd(&g_cand_count, total);
        base = __shfl_sync(0xffffffffu, base, 0);
        int off = base + pref - cl;
        #pragma unroll
        for (int i = 0; i < 32; i++) {
            if (v[i] <= thr) {
                if (off < CAND_CAP) {
                    g_cand_row[off] = row;
                    g_cand_code[off] = i * 32 + lane;
                }
                off++;
            }
        }

        // softmax accumulation on approx distances
        float s = 0.f;
        #pragma unroll
        for (int i = 0; i < 32; i++) { v[i] = __expf((m - v[i]) * 20.0f); s += v[i]; }
        #pragma unroll
        for (int o = 16; o; o >>= 1) s += __shfl_xor_sync(0xffffffffu, s, o);
        float inv = 1.0f / s;
        #pragma unroll
        for (int i = 0; i < 32; i++) colacc[i] = __fmaf_rn(v[i], inv, colacc[i]);
    }
    #pragma unroll
    for (int i = 0; i < 32; i++)
        atomicAdd(&g_colsum[i * 32 + lane], colacc[i]);
}

// ---------------- kernel 4: exact recompute of candidates --------------------
__global__ __launch_bounds__(256) void resolve_kernel(const float* __restrict__ Z,
                                                      const float* __restrict__ E) {
    int count = g_cand_count;
    if (count > CAND_CAP) count = CAND_CAP;
    for (int i = blockIdx.x * blockDim.x + threadIdx.x; i < count;
         i += gridDim.x * blockDim.x) {
        int row = g_cand_row[i];
        int code = g_cand_code[i];
        const float4* z4 = (const float4*)(Z + (size_t)row * DIM);
        const float4* e4 = (const float4*)(E + (size_t)code * DIM);
        float acc = 0.f;
        #pragma unroll 8
        for (int d = 0; d < 64; d++) {
            float4 a = z4[d], b = e4[d];
            acc = __fmaf_rn(a.x, b.x, acc);
            acc = __fmaf_rn(a.y, b.y, acc);
            acc = __fmaf_rn(a.z, b.z, acc);
            acc = __fmaf_rn(a.w, b.w, acc);
        }
        float t1 = __fadd_rn(g_sz[row], g_se[code]);
        float dd = __fadd_rn(t1, -(2.0f * acc));
        unsigned long long key =
            ((unsigned long long)__float_as_uint(dd) << 32) | (unsigned)code;
        atomicMin(&g_key[row], key);
    }
}

// ---------------- kernel 5: gather quantized, straight-through, loss ---------
__global__ __launch_bounds__(256) void gather_loss_kernel(
    const float* __restrict__ Z, const float* __restrict__ E,
    float* __restrict__ out_q, float* __restrict__ out_idx_f) {
    const int row = blockIdx.x;
    const int t = threadIdx.x;
    const int idx = (int)(g_key[row] & 0xFFFFFFFFu);
    float e  = E[(size_t)idx * DIM + t];
    float zv = Z[(size_t)row * DIM + t];
    float diff = __fadd_rn(e, -zv);
    out_q[(size_t)row * DIM + t] = __fadd_rn(zv, diff);
    float sq = diff * diff;
    if (t == 0) out_idx_f[row] = (float)idx;

    __shared__ float red[8];
    #pragma unroll
    for (int o = 16; o; o >>= 1) sq += __shfl_xor_sync(0xffffffffu, sq, o);
    if ((t & 31) == 0) red[t >> 5] = sq;
    __syncthreads();
    if (t < 8) {
        float x = red[t];
        #pragma unroll
        for (int o = 4; o; o >>= 1) x += __shfl_xor_sync(0xffu, x, o);
        if (t == 0) atomicAdd(&g_loss, x);
    }
}

// ---------------- kernel 6: finalize ------------------------------------------
__global__ void finalize_kernel(float* __restrict__ out_loss,
                                float* __restrict__ out_avg) {
    int k = blockIdx.x * blockDim.x + threadIdx.x;
    if (k < NCODES) out_avg[k] = g_colsum[k] * (1.0f / (float)NROWS);
    if (k == 0) {
        float mse = g_loss * (1.0f / (float)((size_t)NROWS * DIM));
        out_loss[0] = __fadd_rn(mse, 0.25f * mse);
    }
}

// -----------------------------------------------------------------------------
extern "C" void kernel_launch(void* const* d_in, const int* in_sizes, int n_in,
                              void* d_out, int out_size) {
    const float* Z = (const float*)d_in[0];
    const float* E = (const float*)d_in[1];
    if (n_in >= 2 && in_sizes[0] == NCODES * DIM && in_sizes[1] == NROWS * DIM) {
        E = (const float*)d_in[0];
        Z = (const float*)d_in[1];
    }

    float* out       = (float*)d_out;
    float* out_q     = out;                              // 8388608
    float* out_loss  = out + (size_t)NROWS * DIM;        // 1
    float* out_idx_f = out_loss + 1;                     // 32768
    float* out_avg   = out_idx_f + NROWS;                // 1024

    cudaFuncSetAttribute(gemm_mma_kernel,
                         cudaFuncAttributeMaxDynamicSharedMemorySize, SM_TOT);

    prep_se_kernel<<<(NCODES + 255) / 256, 256>>>(E);
    prep_sz_kernel<<<NROWS / 256, 256>>>(Z);
    dim3 grid(NCODES / 128, NROWS / 128);                // (8, 256)
    gemm_mma_kernel<<<grid, 256, SM_TOT>>>();
    softmax_kernel<<<NROWS / 128, 256>>>();
    resolve_kernel<<<1024, 256>>>(Z, E);
    gather_loss_kernel<<<NROWS, 256>>>(Z, E, out_q, out_idx_f);
    finalize_kernel<<<(NCODES + 255) / 256, 256>>>(out_loss, out_avg);
}

// round 6
// speedup vs baseline: 1.9155x; 1.2050x over previous
#include <cuda_runtime.h>
#include <cuda_bf16.h>
#include <cstdint>
#include <cstddef>

// Problem constants
#define NROWS   32768
#define NCODES  1024
#define DIM     256
#define MARGIN  3e-3f
#define CAND_CAP (1 << 21)
#define BLK_CAND 6144

// ---------------- scratch (static device globals) ---------------------------
__device__ __nv_bfloat16 g_Zb[(size_t)NROWS * DIM];   // 16 MB
__device__ __nv_bfloat16 g_Eb[(size_t)NCODES * DIM];  // 0.5 MB
__device__ float g_se[NCODES];
__device__ float g_sz[NROWS];
__device__ float g_colsum[NCODES];
__device__ float g_loss;
__device__ unsigned long long g_key[NROWS];           // packed (dist_bits, code)
__device__ int   g_cand_count;
__device__ int   g_cand_row[CAND_CAP];
__device__ int   g_cand_code[CAND_CAP];

__device__ __forceinline__ uint32_t smem_u32(const void* p) {
    uint32_t a;
    asm("{ .reg .u64 t; cvta.to.shared.u64 t, %1; cvt.u32.u64 %0, t; }"
        : "=r"(a) : "l"(p));
    return a;
}
__device__ __forceinline__ uint32_t pack_bf2(float lo, float hi) {
    __nv_bfloat162 h = __floats2bfloat162_rn(lo, hi);
    return *(uint32_t*)&h;
}
__device__ __forceinline__ float bf_lo(uint32_t u) {
    __nv_bfloat162 h = *(__nv_bfloat162*)&u; return __bfloat162float(h.x);
}
__device__ __forceinline__ float bf_hi(uint32_t u) {
    __nv_bfloat162 h = *(__nv_bfloat162*)&u; return __bfloat162float(h.y);
}

#define CP_ASYNC16(dst, src) \
    asm volatile("cp.async.cg.shared.global [%0], [%1], 16;" \
                 :: "r"(dst), "l"(src) : "memory")
#define CP_COMMIT() asm volatile("cp.async.commit_group;" ::: "memory")
#define CP_WAIT1()  asm volatile("cp.async.wait_group 1;" ::: "memory")
#define CP_WAIT0()  asm volatile("cp.async.wait_group 0;" ::: "memory")

// ---------------- kernel 1: se (exact chain) + E->bf16 + zero accums ---------
__global__ void prep_se_kernel(const float* __restrict__ E) {
    int code = blockIdx.x * blockDim.x + threadIdx.x;
    if (code < NCODES) {
        const float4* e4 = (const float4*)(E + (size_t)code * DIM);
        uint4* eb = (uint4*)(g_Eb + (size_t)code * DIM);
        float s = 0.f;
        for (int i = 0; i < 64; i += 2) {
            float4 a = e4[i], b = e4[i + 1];
            s = __fadd_rn(s, __fmul_rn(a.x, a.x));
            s = __fadd_rn(s, __fmul_rn(a.y, a.y));
            s = __fadd_rn(s, __fmul_rn(a.z, a.z));
            s = __fadd_rn(s, __fmul_rn(a.w, a.w));
            s = __fadd_rn(s, __fmul_rn(b.x, b.x));
            s = __fadd_rn(s, __fmul_rn(b.y, b.y));
            s = __fadd_rn(s, __fmul_rn(b.z, b.z));
            s = __fadd_rn(s, __fmul_rn(b.w, b.w));
            uint4 o;
            o.x = pack_bf2(a.x, a.y); o.y = pack_bf2(a.z, a.w);
            o.z = pack_bf2(b.x, b.y); o.w = pack_bf2(b.z, b.w);
            eb[i >> 1] = o;
        }
        g_se[code] = s;
        g_colsum[code] = 0.f;
    }
    if (blockIdx.x == 0 && threadIdx.x == 0) { g_loss = 0.f; g_cand_count = 0; }
}

// ---------------- kernel 1b: sz (exact chain) + Z->bf16 + key init -----------
__global__ void prep_sz_kernel(const float* __restrict__ Z) {
    int row = blockIdx.x * blockDim.x + threadIdx.x;
    if (row >= NROWS) return;
    const float4* z4 = (const float4*)(Z + (size_t)row * DIM);
    uint4* zb = (uint4*)(g_Zb + (size_t)row * DIM);
    float s = 0.f;
    for (int i = 0; i < 64; i += 2) {
        float4 a = z4[i], b = z4[i + 1];
        s = __fadd_rn(s, __fmul_rn(a.x, a.x));
        s = __fadd_rn(s, __fmul_rn(a.y, a.y));
        s = __fadd_rn(s, __fmul_rn(a.z, a.z));
        s = __fadd_rn(s, __fmul_rn(a.w, a.w));
        s = __fadd_rn(s, __fmul_rn(b.x, b.x));
        s = __fadd_rn(s, __fmul_rn(b.y, b.y));
        s = __fadd_rn(s, __fmul_rn(b.z, b.z));
        s = __fadd_rn(s, __fmul_rn(b.w, b.w));
        uint4 o;
        o.x = pack_bf2(a.x, a.y); o.y = pack_bf2(a.z, a.w);
        o.z = pack_bf2(b.x, b.y); o.w = pack_bf2(b.z, b.w);
        zb[i >> 1] = o;
    }
    g_sz[row] = s;
    g_key[row] = 0xFFFFFFFFFFFFFFFFull;
}

// ---------------- kernel 2: FUSED bf16 GEMM + softmax + candidates -----------
// Block: 64 rows x ALL 1024 codes. 256 threads = 8 warps (2M x 4N), warp tile
// 32x32 via m16n8k16. B streamed as 32 ktiles (8 chunks of 128 codes x
// 4 k-quarters of 64 k) through a 3-stage cp.async ring.
// smem byte offsets:
#define SM_B    0                       // 3 * 16384 = 49152 (ring; later cand list)
#define SM_A    49152                   // 64 * 512 = 32768
#define SM_EXP  81920                   // 64 * 1024 * 2 = 131072
#define SM_MC   212992                  // 8*64 f32 anchors (later thr) = 2048
#define SM_PC   215040                  // 8*64 f32 psums (later f) = 2048
#define SM_SE   217088                  // 1024 f32
#define SM_SZ   221184                  // 64 f32
#define SM_CNT  221440
#define SM_BASE 221444
#define SM_TOT  221504

__device__ __forceinline__ void load_b_tile(uint32_t sb, int tid, int t) {
    const int c = t >> 2, kq = t & 3;            // c in [0,8), kq in [0,4)
    const uint32_t bufb = sb + SM_B + (uint32_t)(t % 3) * 16384u;
    #pragma unroll
    for (int i = 0; i < 4; i++) {
        int linear = i * 256 + tid;              // row = linear>>3, c16 = linear&7
        int row = linear >> 3, c16 = linear & 7;
        uint32_t dst = bufb + (uint32_t)row * 128u +
                       (uint32_t)((c16 * 16) ^ ((row & 7) << 4));
        const void* src = g_Eb + (size_t)(c * 128 + row) * DIM + kq * 64 + c16 * 8;
        CP_ASYNC16(dst, src);
    }
}

__global__ __launch_bounds__(256) void fused_kernel() {
    extern __shared__ __align__(1024) char smem[];
    const uint32_t sb = smem_u32(smem);
    const int tid = threadIdx.x, wid = tid >> 5, lane = tid & 31;
    const int m0 = blockIdx.x * 64;
    const int wm = (wid >> 2) * 32, wn = (wid & 3) * 32;

    // prologue scalar loads + inits
    if (tid < 64) ((float*)(smem + SM_SZ))[tid] = g_sz[m0 + tid];
    #pragma unroll
    for (int i = 0; i < 4; i++) ((float*)(smem + SM_SE))[i * 256 + tid] = g_se[i * 256 + tid];
    #pragma unroll
    for (int i = 0; i < 2; i++) {
        ((uint32_t*)(smem + SM_MC))[i * 256 + tid] = 0x7F7FFFFFu;   // +FLT_MAX
        ((float*)(smem + SM_PC))[i * 256 + tid] = 0.f;
    }
    if (tid == 0) *((int*)(smem + SM_CNT)) = 0;

    // A tile via cp.async (part of group 0 with B tile 0)
    #pragma unroll
    for (int i = 0; i < 8; i++) {
        int linear = i * 256 + tid;              // row = linear>>5, c16 = linear&31
        int row = linear >> 5, c16 = linear & 31;
        uint32_t dst = sb + SM_A + (uint32_t)row * 512u +
                       (uint32_t)((c16 * 16) ^ ((row & 7) << 4));
        const void* src = g_Zb + (size_t)(m0 + row) * DIM + c16 * 8;
        CP_ASYNC16(dst, src);
    }
    load_b_tile(sb, tid, 0); CP_COMMIT();        // group 0: A + tile0
    load_b_tile(sb, tid, 1); CP_COMMIT();        // group 1: tile1

    float acc[2][4][4];
    const int r0 = lane >> 2, c0 = (lane & 3) * 2;

    for (int t = 0; t < 32; t++) {
        const int c = t >> 2, kq = t & 3;
        CP_WAIT1();
        __syncthreads();
        if (t + 2 < 32) load_b_tile(sb, tid, t + 2);
        CP_COMMIT();

        if (kq == 0) {
            #pragma unroll
            for (int i = 0; i < 2; i++)
                #pragma unroll
                for (int j = 0; j < 4; j++)
                    #pragma unroll
                    for (int e = 0; e < 4; e++) acc[i][j][e] = 0.f;
        }

        const uint32_t bufb = sb + SM_B + (uint32_t)(t % 3) * 16384u;
        #pragma unroll
        for (int ks = 0; ks < 4; ks++) {
            uint32_t a[2][4], b[4][2];
            const int ak = kq * 64 + ks * 16 + ((lane >> 4) << 3);
            #pragma unroll
            for (int mt = 0; mt < 2; mt++) {
                const int ar = wm + mt * 16 + (lane & 15);
                uint32_t addr = sb + SM_A + (uint32_t)ar * 512u +
                                (uint32_t)((ak * 2) ^ ((ar & 7) << 4));
                asm volatile("ldmatrix.sync.aligned.m8n8.x4.shared.b16 {%0,%1,%2,%3}, [%4];"
                             : "=r"(a[mt][0]), "=r"(a[mt][1]), "=r"(a[mt][2]), "=r"(a[mt][3])
                             : "r"(addr));
            }
            const int bk = ks * 16 + (((lane >> 3) & 1) << 3);
            #pragma unroll
            for (int nt = 0; nt < 4; nt++) {
                const int br = wn + nt * 8 + (lane & 7);
                uint32_t addr = bufb + (uint32_t)br * 128u +
                                (uint32_t)((bk * 2) ^ ((br & 7) << 4));
                asm volatile("ldmatrix.sync.aligned.m8n8.x2.shared.b16 {%0,%1}, [%2];"
                             : "=r"(b[nt][0]), "=r"(b[nt][1]) : "r"(addr));
            }
            #pragma unroll
            for (int mt = 0; mt < 2; mt++)
                #pragma unroll
                for (int nt = 0; nt < 4; nt++)
                    asm volatile(
                        "mma.sync.aligned.m16n8k16.row.col.f32.bf16.bf16.f32 "
                        "{%0,%1,%2,%3}, {%4,%5,%6,%7}, {%8,%9}, {%0,%1,%2,%3};"
                        : "+f"(acc[mt][nt][0]), "+f"(acc[mt][nt][1]),
                          "+f"(acc[mt][nt][2]), "+f"(acc[mt][nt][3])
                        : "r"(a[mt][0]), "r"(a[mt][1]), "r"(a[mt][2]), "r"(a[mt][3]),
                          "r"(b[nt][0]), "r"(b[nt][1]));
        }

        if (kq == 3) {
            // chunk epilogue: d in place of acc, chunk-row-min, exp store, psum
            float* sz = (float*)(smem + SM_SZ);
            float* se = (float*)(smem + SM_SE);
            uint32_t* mc = (uint32_t*)(smem + SM_MC) + c * 64;
            float* pc = (float*)(smem + SM_PC) + c * 64;
            #pragma unroll
            for (int mt = 0; mt < 2; mt++) {
                #pragma unroll
                for (int rs = 0; rs < 2; rs++) {
                    const int row = wm + mt * 16 + rs * 8 + r0;
                    const float szv = sz[row];
                    float mn = 3.4e38f;
                    #pragma unroll
                    for (int nt = 0; nt < 4; nt++) {
                        const int col = c * 128 + wn + nt * 8 + c0;
                        float d0 = szv + se[col]     - 2.f * acc[mt][nt][rs * 2];
                        float d1 = szv + se[col + 1] - 2.f * acc[mt][nt][rs * 2 + 1];
                        acc[mt][nt][rs * 2]     = d0;
                        acc[mt][nt][rs * 2 + 1] = d1;
                        mn = fminf(mn, fminf(d0, d1));
                    }
                    mn = fminf(mn, __shfl_xor_sync(0xffffffffu, mn, 1));
                    mn = fminf(mn, __shfl_xor_sync(0xffffffffu, mn, 2));
                    if ((lane & 3) == 0)
                        atomicMin(&mc[row], __float_as_uint(mn));
                }
            }
            __syncthreads();
            #pragma unroll
            for (int mt = 0; mt < 2; mt++) {
                #pragma unroll
                for (int rs = 0; rs < 2; rs++) {
                    const int row = wm + mt * 16 + rs * 8 + r0;
                    const float mm = __uint_as_float(mc[row]);
                    float ps = 0.f;
                    #pragma unroll
                    for (int nt = 0; nt < 4; nt++) {
                        const int colL = wn + nt * 8 + c0;
                        float e0 = __expf((mm - acc[mt][nt][rs * 2]) * 20.f);
                        float e1 = __expf((mm - acc[mt][nt][rs * 2 + 1]) * 20.f);
                        ps += e0 + e1;
                        uint32_t pk = pack_bf2(e0, e1);
                        uint32_t cb = (uint32_t)((c * 128 + colL) * 2);
                        *(uint32_t*)(smem + SM_EXP + row * 2048 +
                                     (cb ^ (uint32_t)((row & 7) << 4))) = pk;
                    }
                    ps += __shfl_xor_sync(0xffffffffu, ps, 1);
                    ps += __shfl_xor_sync(0xffffffffu, ps, 2);
                    if ((lane & 3) == 0) atomicAdd(&pc[row], ps);
                }
            }
        }
    }
    CP_WAIT0();
    __syncthreads();

    // per-row tables: m_final, s_final -> f (prob factor), thr (candidate)
    if (tid < 64) {
        const int row = tid;
        float mcv[8], mf = 3.4e38f;
        #pragma unroll
        for (int c = 0; c < 8; c++) {
            mcv[c] = __uint_as_float(((uint32_t*)(smem + SM_MC))[c * 64 + row]);
            mf = fminf(mf, mcv[c]);
        }
        float sf = 0.f;
        #pragma unroll
        for (int c = 0; c < 8; c++)
            sf += ((float*)(smem + SM_PC))[c * 64 + row] * __expf((mf - mcv[c]) * 20.f);
        const float inv = 1.0f / sf;
        #pragma unroll
        for (int c = 0; c < 8; c++) {
            float f = __expf((mf - mcv[c]) * 20.f) * inv;
            float thr = __expf((mcv[c] - mf - MARGIN) * 20.f);  // overflow->inf: no cands
            ((float*)(smem + SM_PC))[c * 64 + row] = f;
            ((float*)(smem + SM_MC))[c * 64 + row] = thr;
        }
    }
    __syncthreads();

    // colsum + candidate scan over smem exp buffer
    {
        const int cch = tid >> 5;                 // chunk of this thread's 4 codes
        const float* fR   = (float*)(smem + SM_PC) + cch * 64;
        const float* thrR = (float*)(smem + SM_MC) + cch * 64;
        int2* cand = (int2*)(smem + SM_B);
        int* cnt = (int*)(smem + SM_CNT);
        float cs0 = 0.f, cs1 = 0.f, cs2 = 0.f, cs3 = 0.f;
        for (int row = 0; row < 64; row++) {
            uint2 v = *(uint2*)(smem + SM_EXP + row * 2048 +
                                (uint32_t)((tid * 8) ^ ((row & 7) << 4)));
            float e0 = bf_lo(v.x), e1 = bf_hi(v.x);
            float e2 = bf_lo(v.y), e3 = bf_hi(v.y);
            float f = fR[row], thr = thrR[row];
            cs0 = __fmaf_rn(e0, f, cs0);
            cs1 = __fmaf_rn(e1, f, cs1);
            cs2 = __fmaf_rn(e2, f, cs2);
            cs3 = __fmaf_rn(e3, f, cs3);
            bool h0 = e0 >= thr, h1 = e1 >= thr, h2 = e2 >= thr, h3 = e3 >= thr;
            if (__ballot_sync(0xffffffffu, h0 | h1 | h2 | h3)) {
                #pragma unroll
                for (int j = 0; j < 4; j++) {
                    bool h = (j == 0) ? h0 : (j == 1) ? h1 : (j == 2) ? h2 : h3;
                    if (h) {
                        int p = atomicAdd(cnt, 1);
                        if (p < BLK_CAND) cand[p] = make_int2(m0 + row, tid * 4 + j);
                    }
                }
            }
        }
        atomicAdd(&g_colsum[tid * 4 + 0], cs0);
        atomicAdd(&g_colsum[tid * 4 + 1], cs1);
        atomicAdd(&g_colsum[tid * 4 + 2], cs2);
        atomicAdd(&g_colsum[tid * 4 + 3], cs3);
        __syncthreads();
        int n = *cnt; if (n > BLK_CAND) n = BLK_CAND;
        if (tid == 0) *((int*)(smem + SM_BASE)) = atomicAdd(&g_cand_count, n);
        __syncthreads();
        const int base = *((int*)(smem + SM_BASE));
        for (int i = tid; i < n; i += 256) {
            int2 e = cand[i];
            int p = base + i;
            if (p < CAND_CAP) { g_cand_row[p] = e.x; g_cand_code[p] = e.y; }
        }
    }
}

// ---------------- kernel 3: exact recompute of candidates --------------------
__global__ __launch_bounds__(256) void resolve_kernel(const float* __restrict__ Z,
                                                      const float* __restrict__ E) {
    int count = g_cand_count;
    if (count > CAND_CAP) count = CAND_CAP;
    for (int i = blockIdx.x * blockDim.x + threadIdx.x; i < count;
         i += gridDim.x * blockDim.x) {
        int row = g_cand_row[i];
        int code = g_cand_code[i];
        const float4* z4 = (const float4*)(Z + (size_t)row * DIM);
        const float4* e4 = (const float4*)(E + (size_t)code * DIM);
        float acc = 0.f;
        #pragma unroll 8
        for (int d = 0; d < 64; d++) {
            float4 a = z4[d], b = e4[d];
            acc = __fmaf_rn(a.x, b.x, acc);
            acc = __fmaf_rn(a.y, b.y, acc);
            acc = __fmaf_rn(a.z, b.z, acc);
            acc = __fmaf_rn(a.w, b.w, acc);
        }
        float t1 = __fadd_rn(g_sz[row], g_se[code]);
        float dd = __fadd_rn(t1, -(2.0f * acc));
        unsigned long long key =
            ((unsigned long long)__float_as_uint(dd) << 32) | (unsigned)code;
        atomicMin(&g_key[row], key);
    }
}

// ---------------- kernel 4: gather quantized, straight-through, loss ---------
__global__ __launch_bounds__(256) void gather_loss_kernel(
    const float* __restrict__ Z, const float* __restrict__ E,
    float* __restrict__ out_q, float* __restrict__ out_idx_f) {
    const int row = blockIdx.x;
    const int t = threadIdx.x;
    const int idx = (int)(g_key[row] & 0xFFFFFFFFu);
    float e  = E[(size_t)idx * DIM + t];
    float zv = Z[(size_t)row * DIM + t];
    float diff = __fadd_rn(e, -zv);
    out_q[(size_t)row * DIM + t] = __fadd_rn(zv, diff);
    float sq = diff * diff;
    if (t == 0) out_idx_f[row] = (float)idx;

    __shared__ float red[8];
    #pragma unroll
    for (int o = 16; o; o >>= 1) sq += __shfl_xor_sync(0xffffffffu, sq, o);
    if ((t & 31) == 0) red[t >> 5] = sq;
    __syncthreads();
    if (t < 8) {
        float x = red[t];
        #pragma unroll
        for (int o = 4; o; o >>= 1) x += __shfl_xor_sync(0xffu, x, o);
        if (t == 0) atomicAdd(&g_loss, x);
    }
}

// ---------------- kernel 5: finalize ------------------------------------------
__global__ void finalize_kernel(float* __restrict__ out_loss,
                                float* __restrict__ out_avg) {
    int k = blockIdx.x * blockDim.x + threadIdx.x;
    if (k < NCODES) out_avg[k] = g_colsum[k] * (1.0f / (float)NROWS);
    if (k == 0) {
        float mse = g_loss * (1.0f / (float)((size_t)NROWS * DIM));
        out_loss[0] = __fadd_rn(mse, 0.25f * mse);
    }
}

// -----------------------------------------------------------------------------
extern "C" void kernel_launch(void* const* d_in, const int* in_sizes, int n_in,
                              void* d_out, int out_size) {
    const float* Z = (const float*)d_in[0];
    const float* E = (const float*)d_in[1];
    if (n_in >= 2 && in_sizes[0] == NCODES * DIM && in_sizes[1] == NROWS * DIM) {
        E = (const float*)d_in[0];
        Z = (const float*)d_in[1];
    }

    float* out       = (float*)d_out;
    float* out_q     = out;                              // 8388608
    float* out_loss  = out + (size_t)NROWS * DIM;        // 1
    float* out_idx_f = out_loss + 1;                     // 32768
    float* out_avg   = out_idx_f + NROWS;                // 1024

    cudaFuncSetAttribute(fused_kernel,
                         cudaFuncAttributeMaxDynamicSharedMemorySize, SM_TOT);

    prep_se_kernel<<<(NCODES + 255) / 256, 256>>>(E);
    prep_sz_kernel<<<NROWS / 256, 256>>>(Z);
    fused_kernel<<<NROWS / 64, 256, SM_TOT>>>();
    resolve_kernel<<<1024, 256>>>(Z, E);
    gather_loss_kernel<<<NROWS, 256>>>(Z, E, out_q, out_idx_f);
    finalize_kernel<<<(NCODES + 255) / 256, 256>>>(out_loss, out_avg);
}

// round 7
// speedup vs baseline: 1.9440x; 1.0149x over previous
#include <cuda_runtime.h>
#include <cuda_bf16.h>
#include <cstdint>
#include <cstddef>

// Problem constants
#define NROWS   32768
#define NCODES  1024
#define DIM     256
#define MARGIN  3e-3f
#define CAND_CAP (1 << 21)
#define BLK_CAND 6144

// ---------------- scratch (static device globals) ---------------------------
__device__ __nv_bfloat16 g_Zb[(size_t)NROWS * DIM];   // 16 MB
__device__ __nv_bfloat16 g_Eb[(size_t)NCODES * DIM];  // 0.5 MB
__device__ float g_se[NCODES];
__device__ float g_sz[NROWS];
__device__ float g_colsum[NCODES];
__device__ float g_loss;
__device__ unsigned long long g_key[NROWS];           // packed (dist_bits, code)
__device__ int   g_cand_count;
__device__ int   g_cand_row[CAND_CAP];
__device__ int   g_cand_code[CAND_CAP];

__device__ __forceinline__ uint32_t smem_u32(const void* p) {
    uint32_t a;
    asm("{ .reg .u64 t; cvta.to.shared.u64 t, %1; cvt.u32.u64 %0, t; }"
        : "=r"(a) : "l"(p));
    return a;
}
__device__ __forceinline__ uint32_t pack_bf2(float lo, float hi) {
    __nv_bfloat162 h = __floats2bfloat162_rn(lo, hi);
    return *(uint32_t*)&h;
}
__device__ __forceinline__ float bf_lo(uint32_t u) {
    __nv_bfloat162 h = *(__nv_bfloat162*)&u; return __bfloat162float(h.x);
}
__device__ __forceinline__ float bf_hi(uint32_t u) {
    __nv_bfloat162 h = *(__nv_bfloat162*)&u; return __bfloat162float(h.y);
}

#define CP_ASYNC16(dst, src) \
    asm volatile("cp.async.cg.shared.global [%0], [%1], 16;" \
                 :: "r"(dst), "l"(src) : "memory")
#define CP_COMMIT() asm volatile("cp.async.commit_group;" ::: "memory")
#define CP_WAIT1()  asm volatile("cp.async.wait_group 1;" ::: "memory")
#define CP_WAIT0()  asm volatile("cp.async.wait_group 0;" ::: "memory")

// ---------------- kernel 1: se (exact chain) + E->bf16 + zero accums ---------
__global__ void prep_se_kernel(const float* __restrict__ E) {
    int code = blockIdx.x * blockDim.x + threadIdx.x;
    if (code < NCODES) {
        const float4* e4 = (const float4*)(E + (size_t)code * DIM);
        uint4* eb = (uint4*)(g_Eb + (size_t)code * DIM);
        float s = 0.f;
        for (int i = 0; i < 64; i += 2) {
            float4 a = e4[i], b = e4[i + 1];
            s = __fadd_rn(s, __fmul_rn(a.x, a.x));
            s = __fadd_rn(s, __fmul_rn(a.y, a.y));
            s = __fadd_rn(s, __fmul_rn(a.z, a.z));
            s = __fadd_rn(s, __fmul_rn(a.w, a.w));
            s = __fadd_rn(s, __fmul_rn(b.x, b.x));
            s = __fadd_rn(s, __fmul_rn(b.y, b.y));
            s = __fadd_rn(s, __fmul_rn(b.z, b.z));
            s = __fadd_rn(s, __fmul_rn(b.w, b.w));
            uint4 o;
            o.x = pack_bf2(a.x, a.y); o.y = pack_bf2(a.z, a.w);
            o.z = pack_bf2(b.x, b.y); o.w = pack_bf2(b.z, b.w);
            eb[i >> 1] = o;
        }
        g_se[code] = s;
        g_colsum[code] = 0.f;
    }
    if (blockIdx.x == 0 && threadIdx.x == 0) { g_loss = 0.f; g_cand_count = 0; }
}

// ---------------- kernel 1b: sz (exact chain) + Z->bf16 + key init -----------
__global__ void prep_sz_kernel(const float* __restrict__ Z) {
    int row = blockIdx.x * blockDim.x + threadIdx.x;
    if (row >= NROWS) return;
    const float4* z4 = (const float4*)(Z + (size_t)row * DIM);
    uint4* zb = (uint4*)(g_Zb + (size_t)row * DIM);
    float s = 0.f;
    for (int i = 0; i < 64; i += 2) {
        float4 a = z4[i], b = z4[i + 1];
        s = __fadd_rn(s, __fmul_rn(a.x, a.x));
        s = __fadd_rn(s, __fmul_rn(a.y, a.y));
        s = __fadd_rn(s, __fmul_rn(a.z, a.z));
        s = __fadd_rn(s, __fmul_rn(a.w, a.w));
        s = __fadd_rn(s, __fmul_rn(b.x, b.x));
        s = __fadd_rn(s, __fmul_rn(b.y, b.y));
        s = __fadd_rn(s, __fmul_rn(b.z, b.z));
        s = __fadd_rn(s, __fmul_rn(b.w, b.w));
        uint4 o;
        o.x = pack_bf2(a.x, a.y); o.y = pack_bf2(a.z, a.w);
        o.z = pack_bf2(b.x, b.y); o.w = pack_bf2(b.z, b.w);
        zb[i >> 1] = o;
    }
    g_sz[row] = s;
    g_key[row] = 0xFFFFFFFFFFFFFFFFull;
}

// ---------------- kernel 2: FUSED bf16 GEMM + softmax + candidates -----------
// Block: 64 rows x ALL 1024 codes. 256 threads = 8 warps (2M x 4N), warp tile
// 32x32 via m16n8k16. B streamed as 32 ktiles (8 chunks of 128 codes x
// 4 k-quarters of 64 k) through a 3-stage cp.async ring.
// smem byte offsets:
#define SM_B    0                       // 3 * 16384 = 49152 (ring; later cand list)
#define SM_A    49152                   // 64 * 512 = 32768
#define SM_EXP  81920                   // 64 * 1024 * 2 = 131072
#define SM_MC   212992                  // 8*64 f32 anchors (later thr) = 2048
#define SM_PC   215040                  // 8*64 f32 psums (later f) = 2048
#define SM_SE   217088                  // 1024 f32
#define SM_SZ   221184                  // 64 f32
#define SM_CNT  221440
#define SM_RC   221504                  // 64 ints: per-row candidate count
#define SM_RF   221760                  // 64 ints: per-row first candidate code
#define SM_TOT  222016

__device__ __forceinline__ void load_b_tile(uint32_t sb, int tid, int t) {
    const int c = t >> 2, kq = t & 3;            // c in [0,8), kq in [0,4)
    const uint32_t bufb = sb + SM_B + (uint32_t)(t % 3) * 16384u;
    #pragma unroll
    for (int i = 0; i < 4; i++) {
        int linear = i * 256 + tid;              // row = linear>>3, c16 = linear&7
        int row = linear >> 3, c16 = linear & 7;
        uint32_t dst = bufb + (uint32_t)row * 128u +
                       (uint32_t)((c16 * 16) ^ ((row & 7) << 4));
        const void* src = g_Eb + (size_t)(c * 128 + row) * DIM + kq * 64 + c16 * 8;
        CP_ASYNC16(dst, src);
    }
}

__global__ __launch_bounds__(256) void fused_kernel() {
    extern __shared__ __align__(1024) char smem[];
    const uint32_t sb = smem_u32(smem);
    const int tid = threadIdx.x, wid = tid >> 5, lane = tid & 31;
    const int m0 = blockIdx.x * 64;
    const int wm = (wid >> 2) * 32, wn = (wid & 3) * 32;

    // prologue scalar loads + inits
    if (tid < 64) {
        ((float*)(smem + SM_SZ))[tid] = g_sz[m0 + tid];
        ((int*)(smem + SM_RC))[tid] = 0;
    }
    #pragma unroll
    for (int i = 0; i < 4; i++) ((float*)(smem + SM_SE))[i * 256 + tid] = g_se[i * 256 + tid];
    #pragma unroll
    for (int i = 0; i < 2; i++) {
        ((uint32_t*)(smem + SM_MC))[i * 256 + tid] = 0x7F7FFFFFu;   // +FLT_MAX
        ((float*)(smem + SM_PC))[i * 256 + tid] = 0.f;
    }
    if (tid == 0) *((int*)(smem + SM_CNT)) = 0;

    // A tile via cp.async (part of group 0 with B tile 0)
    #pragma unroll
    for (int i = 0; i < 8; i++) {
        int linear = i * 256 + tid;              // row = linear>>5, c16 = linear&31
        int row = linear >> 5, c16 = linear & 31;
        uint32_t dst = sb + SM_A + (uint32_t)row * 512u +
                       (uint32_t)((c16 * 16) ^ ((row & 7) << 4));
        const void* src = g_Zb + (size_t)(m0 + row) * DIM + c16 * 8;
        CP_ASYNC16(dst, src);
    }
    load_b_tile(sb, tid, 0); CP_COMMIT();        // group 0: A + tile0
    load_b_tile(sb, tid, 1); CP_COMMIT();        // group 1: tile1

    float acc[2][4][4];
    const int r0 = lane >> 2, c0 = (lane & 3) * 2;

    for (int t = 0; t < 32; t++) {
        const int c = t >> 2, kq = t & 3;
        CP_WAIT1();
        __syncthreads();
        if (t + 2 < 32) load_b_tile(sb, tid, t + 2);
        CP_COMMIT();

        if (kq == 0) {
            #pragma unroll
            for (int i = 0; i < 2; i++)
                #pragma unroll
                for (int j = 0; j < 4; j++)
                    #pragma unroll
                    for (int e = 0; e < 4; e++) acc[i][j][e] = 0.f;
        }

        const uint32_t bufb = sb + SM_B + (uint32_t)(t % 3) * 16384u;
        #pragma unroll
        for (int ks = 0; ks < 4; ks++) {
            uint32_t a[2][4], b[4][2];
            const int ak = kq * 64 + ks * 16 + ((lane >> 4) << 3);
            #pragma unroll
            for (int mt = 0; mt < 2; mt++) {
                const int ar = wm + mt * 16 + (lane & 15);
                uint32_t addr = sb + SM_A + (uint32_t)ar * 512u +
                                (uint32_t)((ak * 2) ^ ((ar & 7) << 4));
                asm volatile("ldmatrix.sync.aligned.m8n8.x4.shared.b16 {%0,%1,%2,%3}, [%4];"
                             : "=r"(a[mt][0]), "=r"(a[mt][1]), "=r"(a[mt][2]), "=r"(a[mt][3])
                             : "r"(addr));
            }
            const int bk = ks * 16 + (((lane >> 3) & 1) << 3);
            #pragma unroll
            for (int nt = 0; nt < 4; nt++) {
                const int br = wn + nt * 8 + (lane & 7);
                uint32_t addr = bufb + (uint32_t)br * 128u +
                                (uint32_t)((bk * 2) ^ ((br & 7) << 4));
                asm volatile("ldmatrix.sync.aligned.m8n8.x2.shared.b16 {%0,%1}, [%2];"
                             : "=r"(b[nt][0]), "=r"(b[nt][1]) : "r"(addr));
            }
            #pragma unroll
            for (int mt = 0; mt < 2; mt++)
                #pragma unroll
                for (int nt = 0; nt < 4; nt++)
                    asm volatile(
                        "mma.sync.aligned.m16n8k16.row.col.f32.bf16.bf16.f32 "
                        "{%0,%1,%2,%3}, {%4,%5,%6,%7}, {%8,%9}, {%0,%1,%2,%3};"
                        : "+f"(acc[mt][nt][0]), "+f"(acc[mt][nt][1]),
                          "+f"(acc[mt][nt][2]), "+f"(acc[mt][nt][3])
                        : "r"(a[mt][0]), "r"(a[mt][1]), "r"(a[mt][2]), "r"(a[mt][3]),
                          "r"(b[nt][0]), "r"(b[nt][1]));
        }

        if (kq == 3) {
            // chunk epilogue: d in place of acc, chunk-row-min, exp store, psum
            float* sz = (float*)(smem + SM_SZ);
            float* se = (float*)(smem + SM_SE);
            uint32_t* mc = (uint32_t*)(smem + SM_MC) + c * 64;
            float* pc = (float*)(smem + SM_PC) + c * 64;
            #pragma unroll
            for (int mt = 0; mt < 2; mt++) {
                #pragma unroll
                for (int rs = 0; rs < 2; rs++) {
                    const int row = wm + mt * 16 + rs * 8 + r0;
                    const float szv = sz[row];
                    float mn = 3.4e38f;
                    #pragma unroll
                    for (int nt = 0; nt < 4; nt++) {
                        const int col = c * 128 + wn + nt * 8 + c0;
                        float d0 = szv + se[col]     - 2.f * acc[mt][nt][rs * 2];
                        float d1 = szv + se[col + 1] - 2.f * acc[mt][nt][rs * 2 + 1];
                        acc[mt][nt][rs * 2]     = d0;
                        acc[mt][nt][rs * 2 + 1] = d1;
                        mn = fminf(mn, fminf(d0, d1));
                    }
                    mn = fminf(mn, __shfl_xor_sync(0xffffffffu, mn, 1));
                    mn = fminf(mn, __shfl_xor_sync(0xffffffffu, mn, 2));
                    if ((lane & 3) == 0)
                        atomicMin(&mc[row], __float_as_uint(mn));
                }
            }
            __syncthreads();
            #pragma unroll
            for (int mt = 0; mt < 2; mt++) {
                #pragma unroll
                for (int rs = 0; rs < 2; rs++) {
                    const int row = wm + mt * 16 + rs * 8 + r0;
                    const float mm = __uint_as_float(mc[row]);
                    float ps = 0.f;
                    #pragma unroll
                    for (int nt = 0; nt < 4; nt++) {
                        const int colL = wn + nt * 8 + c0;
                        float e0 = __expf((mm - acc[mt][nt][rs * 2]) * 20.f);
                        float e1 = __expf((mm - acc[mt][nt][rs * 2 + 1]) * 20.f);
                        ps += e0 + e1;
                        uint32_t pk = pack_bf2(e0, e1);
                        uint32_t cb = (uint32_t)((c * 128 + colL) * 2);
                        *(uint32_t*)(smem + SM_EXP + row * 2048 +
                                     (cb ^ (uint32_t)((row & 7) << 4))) = pk;
                    }
                    ps += __shfl_xor_sync(0xffffffffu, ps, 1);
                    ps += __shfl_xor_sync(0xffffffffu, ps, 2);
                    if ((lane & 3) == 0) atomicAdd(&pc[row], ps);
                }
            }
        }
    }
    CP_WAIT0();
    __syncthreads();

    // per-row tables: m_final, s_final -> f (prob factor), thr (candidate)
    if (tid < 64) {
        const int row = tid;
        float mcv[8], mf = 3.4e38f;
        #pragma unroll
        for (int c = 0; c < 8; c++) {
            mcv[c] = __uint_as_float(((uint32_t*)(smem + SM_MC))[c * 64 + row]);
            mf = fminf(mf, mcv[c]);
        }
        float sf = 0.f;
        #pragma unroll
        for (int c = 0; c < 8; c++)
            sf += ((float*)(smem + SM_PC))[c * 64 + row] * __expf((mf - mcv[c]) * 20.f);
        const float inv = 1.0f / sf;
        #pragma unroll
        for (int c = 0; c < 8; c++) {
            float f = __expf((mf - mcv[c]) * 20.f) * inv;
            float thr = __expf((mcv[c] - mf - MARGIN) * 20.f);  // overflow->inf: no cands
            ((float*)(smem + SM_PC))[c * 64 + row] = f;
            ((float*)(smem + SM_MC))[c * 64 + row] = thr;
        }
    }
    __syncthreads();

    // colsum + candidate scan over smem exp buffer
    {
        const int cch = tid >> 5;                 // chunk of this thread's 4 codes
        const float* fR   = (float*)(smem + SM_PC) + cch * 64;
        const float* thrR = (float*)(smem + SM_MC) + cch * 64;
        int2* cand = (int2*)(smem + SM_B);
        int* cnt = (int*)(smem + SM_CNT);
        int* rowcnt = (int*)(smem + SM_RC);
        int* rowfirst = (int*)(smem + SM_RF);
        float cs0 = 0.f, cs1 = 0.f, cs2 = 0.f, cs3 = 0.f;
        for (int row = 0; row < 64; row++) {
            uint2 v = *(uint2*)(smem + SM_EXP + row * 2048 +
                                (uint32_t)((tid * 8) ^ ((row & 7) << 4)));
            float e0 = bf_lo(v.x), e1 = bf_hi(v.x);
            float e2 = bf_lo(v.y), e3 = bf_hi(v.y);
            float f = fR[row], thr = thrR[row];
            cs0 = __fmaf_rn(e0, f, cs0);
            cs1 = __fmaf_rn(e1, f, cs1);
            cs2 = __fmaf_rn(e2, f, cs2);
            cs3 = __fmaf_rn(e3, f, cs3);
            bool h0 = e0 >= thr, h1 = e1 >= thr, h2 = e2 >= thr, h3 = e3 >= thr;
            if (__ballot_sync(0xffffffffu, h0 | h1 | h2 | h3)) {
                #pragma unroll
                for (int j = 0; j < 4; j++) {
                    bool h = (j == 0) ? h0 : (j == 1) ? h1 : (j == 2) ? h2 : h3;
                    if (h) {
                        int code = tid * 4 + j;
                        int rc = atomicAdd(&rowcnt[row], 1);
                        if (rc == 0) rowfirst[row] = code;
                        int p = atomicAdd(cnt, 1);
                        if (p < BLK_CAND) cand[p] = make_int2(row, code);
                    }
                }
            }
        }
        atomicAdd(&g_colsum[tid * 4 + 0], cs0);
        atomicAdd(&g_colsum[tid * 4 + 1], cs1);
        atomicAdd(&g_colsum[tid * 4 + 2], cs2);
        atomicAdd(&g_colsum[tid * 4 + 3], cs3);
        __syncthreads();

        // single-candidate rows: index is decided, no exact recompute needed
        if (tid < 64 && rowcnt[tid] == 1)
            g_key[m0 + tid] = (unsigned long long)(unsigned)rowfirst[tid];

        // multi-candidate rows: flush their candidates for exact resolve
        int n = *cnt; if (n > BLK_CAND) n = BLK_CAND;
        for (int i = tid; i < n; i += 256) {
            int2 e = cand[i];
            if (rowcnt[e.x] >= 2) {
                int p = atomicAdd(&g_cand_count, 1);
                if (p < CAND_CAP) {
                    g_cand_row[p] = m0 + e.x;
                    g_cand_code[p] = e.y;
                }
            }
        }
    }
}

// ---------------- kernel 3: exact recompute of candidates --------------------
// Strict ascending-k FMA chain (order fixed); loads software-pipelined with an
// 8-slot register window so ~16 loads are in flight (chain stays serial).
__global__ __launch_bounds__(256) void resolve_kernel(const float* __restrict__ Z,
                                                      const float* __restrict__ E) {
    int count = g_cand_count;
    if (count > CAND_CAP) count = CAND_CAP;
    for (int i = blockIdx.x * blockDim.x + threadIdx.x; i < count;
         i += gridDim.x * blockDim.x) {
        int row = g_cand_row[i];
        int code = g_cand_code[i];
        const float4* z4 = (const float4*)(Z + (size_t)row * DIM);
        const float4* e4 = (const float4*)(E + (size_t)code * DIM);
        float4 zr[8], er[8];
        #pragma unroll
        for (int j = 0; j < 8; j++) { zr[j] = z4[j]; er[j] = e4[j]; }
        float acc = 0.f;
        #pragma unroll
        for (int j = 0; j < 64; j++) {
            float4 a = zr[j & 7], b = er[j & 7];
            if (j < 56) { zr[j & 7] = z4[j + 8]; er[j & 7] = e4[j + 8]; }
            acc = __fmaf_rn(a.x, b.x, acc);
            acc = __fmaf_rn(a.y, b.y, acc);
            acc = __fmaf_rn(a.z, b.z, acc);
            acc = __fmaf_rn(a.w, b.w, acc);
        }
        float t1 = __fadd_rn(g_sz[row], g_se[code]);
        float dd = __fadd_rn(t1, -(2.0f * acc));
        unsigned long long key =
            ((unsigned long long)__float_as_uint(dd) << 32) | (unsigned)code;
        atomicMin(&g_key[row], key);
    }
}

// ---------------- kernel 4: gather quantized, straight-through, loss ---------
__global__ __launch_bounds__(256) void gather_loss_kernel(
    const float* __restrict__ Z, const float* __restrict__ E,
    float* __restrict__ out_q, float* __restrict__ out_idx_f) {
    const int row = blockIdx.x;
    const int t = threadIdx.x;
    const int idx = (int)(g_key[row] & 0xFFFFFFFFu);
    float e  = E[(size_t)idx * DIM + t];
    float zv = Z[(size_t)row * DIM + t];
    float diff = __fadd_rn(e, -zv);
    out_q[(size_t)row * DIM + t] = __fadd_rn(zv, diff);
    float sq = diff * diff;
    if (t == 0) out_idx_f[row] = (float)idx;

    __shared__ float red[8];
    #pragma unroll
    for (int o = 16; o; o >>= 1) sq += __shfl_xor_sync(0xffffffffu, sq, o);
    if ((t & 31) == 0) red[t >> 5] = sq;
    __syncthreads();
    if (t < 8) {
        float x = red[t];
        #pragma unroll
        for (int o = 4; o; o >>= 1) x += __shfl_xor_sync(0xffu, x, o);
        if (t == 0) atomicAdd(&g_loss, x);
    }
}

// ---------------- kernel 5: finalize ------------------------------------------
__global__ void finalize_kernel(float* __restrict__ out_loss,
                                float* __restrict__ out_avg) {
    int k = blockIdx.x * blockDim.x + threadIdx.x;
    if (k < NCODES) out_avg[k] = g_colsum[k] * (1.0f / (float)NROWS);
    if (k == 0) {
        float mse = g_loss * (1.0f / (float)((size_t)NROWS * DIM));
        out_loss[0] = __fadd_rn(mse, 0.25f * mse);
    }
}

// -----------------------------------------------------------------------------
extern "C" void kernel_launch(void* const* d_in, const int* in_sizes, int n_in,
                              void* d_out, int out_size) {
    const float* Z = (const float*)d_in[0];
    const float* E = (const float*)d_in[1];
    if (n_in >= 2 && in_sizes[0] == NCODES * DIM && in_sizes[1] == NROWS * DIM) {
        E = (const float*)d_in[0];
        Z = (const float*)d_in[1];
    }

    float* out       = (float*)d_out;
    float* out_q     = out;                              // 8388608
    float* out_loss  = out + (size_t)NROWS * DIM;        // 1
    float* out_idx_f = out_loss + 1;                     // 32768
    float* out_avg   = out_idx_f + NROWS;                // 1024

    cudaFuncSetAttribute(fused_kernel,
                         cudaFuncAttributeMaxDynamicSharedMemorySize, SM_TOT);

    prep_se_kernel<<<(NCODES + 255) / 256, 256>>>(E);
    prep_sz_kernel<<<NROWS / 256, 256>>>(Z);
    fused_kernel<<<NROWS / 64, 256, SM_TOT>>>();
    resolve_kernel<<<512, 256>>>(Z, E);
    gather_loss_kernel<<<NROWS, 256>>>(Z, E, out_q, out_idx_f);
    finalize_kernel<<<(NCODES + 255) / 256, 256>>>(out_loss, out_avg);
}

// round 8
// speedup vs baseline: 2.0866x; 1.0734x over previous
#include <cuda_runtime.h>
#include <cuda_bf16.h>
#include <cstdint>
#include <cstddef>

// Problem constants
#define NROWS   32768
#define NCODES  1024
#define DIM     256
#define MARGIN  3e-3f
#define CAND_CAP (1 << 21)
#define BLK_CAND 6144

// ---------------- scratch (static device globals) ---------------------------
__device__ __nv_bfloat16 g_Zb[(size_t)NROWS * DIM];   // 16 MB
__device__ __nv_bfloat16 g_Eb[(size_t)NCODES * DIM];  // 0.5 MB
__device__ float g_se[NCODES];
__device__ float g_sz[NROWS];
__device__ float g_colsum[NCODES];
__device__ float g_loss;
__device__ unsigned long long g_key[NROWS];           // packed (dist_bits, code)
__device__ int   g_cand_count;
__device__ int   g_cand_row[CAND_CAP];
__device__ int   g_cand_code[CAND_CAP];

__device__ __forceinline__ uint32_t smem_u32(const void* p) {
    uint32_t a;
    asm("{ .reg .u64 t; cvta.to.shared.u64 t, %1; cvt.u32.u64 %0, t; }"
        : "=r"(a) : "l"(p));
    return a;
}
__device__ __forceinline__ uint32_t pack_bf2(float lo, float hi) {
    __nv_bfloat162 h = __floats2bfloat162_rn(lo, hi);
    return *(uint32_t*)&h;
}
__device__ __forceinline__ float bf_lo(uint32_t u) {
    __nv_bfloat162 h = *(__nv_bfloat162*)&u; return __bfloat162float(h.x);
}
__device__ __forceinline__ float bf_hi(uint32_t u) {
    __nv_bfloat162 h = *(__nv_bfloat162*)&u; return __bfloat162float(h.y);
}

#define CP_ASYNC16(dst, src) \
    asm volatile("cp.async.cg.shared.global [%0], [%1], 16;" \
                 :: "r"(dst), "l"(src) : "memory")
#define CP_COMMIT() asm volatile("cp.async.commit_group;" ::: "memory")
#define CP_WAIT1()  asm volatile("cp.async.wait_group 1;" ::: "memory")
#define CP_WAIT0()  asm volatile("cp.async.wait_group 0;" ::: "memory")

// ---------------- kernel 1: se (exact chain) + E->bf16 + zero accums ---------
__global__ void prep_se_kernel(const float* __restrict__ E) {
    int code = blockIdx.x * blockDim.x + threadIdx.x;
    if (code < NCODES) {
        const float4* e4 = (const float4*)(E + (size_t)code * DIM);
        uint4* eb = (uint4*)(g_Eb + (size_t)code * DIM);
        float s = 0.f;
        for (int i = 0; i < 64; i += 2) {
            float4 a = e4[i], b = e4[i + 1];
            s = __fadd_rn(s, __fmul_rn(a.x, a.x));
            s = __fadd_rn(s, __fmul_rn(a.y, a.y));
            s = __fadd_rn(s, __fmul_rn(a.z, a.z));
            s = __fadd_rn(s, __fmul_rn(a.w, a.w));
            s = __fadd_rn(s, __fmul_rn(b.x, b.x));
            s = __fadd_rn(s, __fmul_rn(b.y, b.y));
            s = __fadd_rn(s, __fmul_rn(b.z, b.z));
            s = __fadd_rn(s, __fmul_rn(b.w, b.w));
            uint4 o;
            o.x = pack_bf2(a.x, a.y); o.y = pack_bf2(a.z, a.w);
            o.z = pack_bf2(b.x, b.y); o.w = pack_bf2(b.z, b.w);
            eb[i >> 1] = o;
        }
        g_se[code] = s;
        g_colsum[code] = 0.f;
    }
    if (blockIdx.x == 0 && threadIdx.x == 0) { g_loss = 0.f; g_cand_count = 0; }
}

// ---------------- kernel 1b: sz (exact chain) + Z->bf16 + key init -----------
__global__ void prep_sz_kernel(const float* __restrict__ Z) {
    int row = blockIdx.x * blockDim.x + threadIdx.x;
    if (row >= NROWS) return;
    const float4* z4 = (const float4*)(Z + (size_t)row * DIM);
    uint4* zb = (uint4*)(g_Zb + (size_t)row * DIM);
    float s = 0.f;
    for (int i = 0; i < 64; i += 2) {
        float4 a = z4[i], b = z4[i + 1];
        s = __fadd_rn(s, __fmul_rn(a.x, a.x));
        s = __fadd_rn(s, __fmul_rn(a.y, a.y));
        s = __fadd_rn(s, __fmul_rn(a.z, a.z));
        s = __fadd_rn(s, __fmul_rn(a.w, a.w));
        s = __fadd_rn(s, __fmul_rn(b.x, b.x));
        s = __fadd_rn(s, __fmul_rn(b.y, b.y));
        s = __fadd_rn(s, __fmul_rn(b.z, b.z));
        s = __fadd_rn(s, __fmul_rn(b.w, b.w));
        uint4 o;
        o.x = pack_bf2(a.x, a.y); o.y = pack_bf2(a.z, a.w);
        o.z = pack_bf2(b.x, b.y); o.w = pack_bf2(b.z, b.w);
        zb[i >> 1] = o;
    }
    g_sz[row] = s;
    g_key[row] = 0xFFFFFFFFFFFFFFFFull;
}

// ---------------- kernel 2: FUSED bf16 GEMM + softmax + candidates -----------
// Block: 64 rows x ALL 1024 codes. 256 threads = 8 warps (2M x 4N), warp tile
// 32x32 via m16n8k16. B streamed as 32 ktiles (8 chunks x 4 k-quarters)
// through a 3-stage cp.async ring. Softmax uses per-(chunk,warpcol) PIECE
// anchors -> no cross-warp sync/atomics in the mainloop epilogue.
// smem byte offsets:
#define SM_B    0                       // 3 * 16384 = 49152 (ring; later cand list)
#define SM_A    49152                   // 64 * 512 = 32768
#define SM_EXP  81920                   // 64 * 1024 * 2 = 131072
#define SM_MCW  212992                  // 32 pieces * 64 rows f32 = 8192 (later unused)
#define SM_PSW  221184                  // 32*64 f32 psums = 8192 (later packed f/thr)
#define SM_SE   229376                  // 1024 bf16 = 2048
#define SM_SZ   231424                  // 64 f32 = 256
#define SM_CNT  231680
#define SM_RC   231684                  // 64 ints: per-row candidate count
#define SM_RF   231940                  // 64 ints: per-row first candidate code
#define SM_TOT  232256

__device__ __forceinline__ void load_b_tile(uint32_t sb, int tid, int t) {
    const int c = t >> 2, kq = t & 3;            // c in [0,8), kq in [0,4)
    const uint32_t bufb = sb + SM_B + (uint32_t)(t % 3) * 16384u;
    #pragma unroll
    for (int i = 0; i < 4; i++) {
        int linear = i * 256 + tid;              // row = linear>>3, c16 = linear&7
        int row = linear >> 3, c16 = linear & 7;
        uint32_t dst = bufb + (uint32_t)row * 128u +
                       (uint32_t)((c16 * 16) ^ ((row & 7) << 4));
        const void* src = g_Eb + (size_t)(c * 128 + row) * DIM + kq * 64 + c16 * 8;
        CP_ASYNC16(dst, src);
    }
}

__global__ __launch_bounds__(256) void fused_kernel() {
    extern __shared__ __align__(1024) char smem[];
    const uint32_t sb = smem_u32(smem);
    const int tid = threadIdx.x, wid = tid >> 5, lane = tid & 31;
    const int m0 = blockIdx.x * 64;
    const int wm = (wid >> 2) * 32, wn = (wid & 3) * 32, wcol = wid & 3;

    // prologue scalar loads + inits
    if (tid < 64) {
        ((float*)(smem + SM_SZ))[tid] = g_sz[m0 + tid];
        ((int*)(smem + SM_RC))[tid] = 0;
    }
    #pragma unroll
    for (int i = 0; i < 4; i++)
        ((__nv_bfloat16*)(smem + SM_SE))[i * 256 + tid] =
            __float2bfloat16(g_se[i * 256 + tid]);
    if (tid == 0) *((int*)(smem + SM_CNT)) = 0;

    // A tile via cp.async (part of group 0 with B tile 0)
    #pragma unroll
    for (int i = 0; i < 8; i++) {
        int linear = i * 256 + tid;              // row = linear>>5, c16 = linear&31
        int row = linear >> 5, c16 = linear & 31;
        uint32_t dst = sb + SM_A + (uint32_t)row * 512u +
                       (uint32_t)((c16 * 16) ^ ((row & 7) << 4));
        const void* src = g_Zb + (size_t)(m0 + row) * DIM + c16 * 8;
        CP_ASYNC16(dst, src);
    }
    load_b_tile(sb, tid, 0); CP_COMMIT();        // group 0: A + tile0
    load_b_tile(sb, tid, 1); CP_COMMIT();        // group 1: tile1

    float acc[2][4][4];
    const int r0 = lane >> 2, c0 = (lane & 3) * 2;

    for (int t = 0; t < 32; t++) {
        const int c = t >> 2, kq = t & 3;
        CP_WAIT1();
        __syncthreads();
        if (t + 2 < 32) load_b_tile(sb, tid, t + 2);
        CP_COMMIT();

        if (kq == 0) {
            #pragma unroll
            for (int i = 0; i < 2; i++)
                #pragma unroll
                for (int j = 0; j < 4; j++)
                    #pragma unroll
                    for (int e = 0; e < 4; e++) acc[i][j][e] = 0.f;
        }

        const uint32_t bufb = sb + SM_B + (uint32_t)(t % 3) * 16384u;
        #pragma unroll
        for (int ks = 0; ks < 4; ks++) {
            uint32_t a[2][4], b[4][2];
            const int ak = kq * 64 + ks * 16 + ((lane >> 4) << 3);
            #pragma unroll
            for (int mt = 0; mt < 2; mt++) {
                const int ar = wm + mt * 16 + (lane & 15);
                uint32_t addr = sb + SM_A + (uint32_t)ar * 512u +
                                (uint32_t)((ak * 2) ^ ((ar & 7) << 4));
                asm volatile("ldmatrix.sync.aligned.m8n8.x4.shared.b16 {%0,%1,%2,%3}, [%4];"
                             : "=r"(a[mt][0]), "=r"(a[mt][1]), "=r"(a[mt][2]), "=r"(a[mt][3])
                             : "r"(addr));
            }
            const int bk = ks * 16 + (((lane >> 3) & 1) << 3);
            #pragma unroll
            for (int nt = 0; nt < 4; nt++) {
                const int br = wn + nt * 8 + (lane & 7);
                uint32_t addr = bufb + (uint32_t)br * 128u +
                                (uint32_t)((bk * 2) ^ ((br & 7) << 4));
                asm volatile("ldmatrix.sync.aligned.m8n8.x2.shared.b16 {%0,%1}, [%2];"
                             : "=r"(b[nt][0]), "=r"(b[nt][1]) : "r"(addr));
            }
            #pragma unroll
            for (int mt = 0; mt < 2; mt++)
                #pragma unroll
                for (int nt = 0; nt < 4; nt++)
                    asm volatile(
                        "mma.sync.aligned.m16n8k16.row.col.f32.bf16.bf16.f32 "
                        "{%0,%1,%2,%3}, {%4,%5,%6,%7}, {%8,%9}, {%0,%1,%2,%3};"
                        : "+f"(acc[mt][nt][0]), "+f"(acc[mt][nt][1]),
                          "+f"(acc[mt][nt][2]), "+f"(acc[mt][nt][3])
                        : "r"(a[mt][0]), "r"(a[mt][1]), "r"(a[mt][2]), "r"(a[mt][3]),
                          "r"(b[nt][0]), "r"(b[nt][1]));
        }

        if (kq == 3) {
            // piece epilogue (warp-local: no sync, no atomics)
            const float* sz = (const float*)(smem + SM_SZ);
            const __nv_bfloat16* seb = (const __nv_bfloat16*)(smem + SM_SE);
            float* mcw = (float*)(smem + SM_MCW) + (c * 4 + wcol) * 64;
            float* psw = (float*)(smem + SM_PSW) + (c * 4 + wcol) * 64;
            #pragma unroll
            for (int mt = 0; mt < 2; mt++) {
                #pragma unroll
                for (int rs = 0; rs < 2; rs++) {
                    const int row = wm + mt * 16 + rs * 8 + r0;
                    const float szv = sz[row];
                    float d[8];
                    float mn = 3.4e38f;
                    #pragma unroll
                    for (int nt = 0; nt < 4; nt++) {
                        const int col = c * 128 + wn + nt * 8 + c0;
                        float d0 = szv + __bfloat162float(seb[col])
                                   - 2.f * acc[mt][nt][rs * 2];
                        float d1 = szv + __bfloat162float(seb[col + 1])
                                   - 2.f * acc[mt][nt][rs * 2 + 1];
                        d[nt * 2] = d0; d[nt * 2 + 1] = d1;
                        mn = fminf(mn, fminf(d0, d1));
                    }
                    mn = fminf(mn, __shfl_xor_sync(0xffffffffu, mn, 1));
                    mn = fminf(mn, __shfl_xor_sync(0xffffffffu, mn, 2));
                    float ps = 0.f;
                    #pragma unroll
                    for (int nt = 0; nt < 4; nt++) {
                        const int colL = wn + nt * 8 + c0;
                        float e0 = __expf((mn - d[nt * 2]) * 20.f);
                        float e1 = __expf((mn - d[nt * 2 + 1]) * 20.f);
                        ps += e0 + e1;
                        uint32_t pk = pack_bf2(e0, e1);
                        uint32_t cb = (uint32_t)((c * 128 + colL) * 2);
                        *(uint32_t*)(smem + SM_EXP + row * 2048 +
                                     (cb ^ (uint32_t)((row & 7) << 4))) = pk;
                    }
                    ps += __shfl_xor_sync(0xffffffffu, ps, 1);
                    ps += __shfl_xor_sync(0xffffffffu, ps, 2);
                    if ((lane & 3) == 0) { mcw[row] = mn; psw[row] = ps; }
                }
            }
        }
    }
    CP_WAIT0();
    __syncthreads();

    // per-row finalize: exact regroup of 32 piece anchors -> f,thr per piece
    if (tid < 64) {
        const int row = tid;
        float mv[32], mf = 3.4e38f;
        #pragma unroll
        for (int p = 0; p < 32; p++) {
            mv[p] = ((float*)(smem + SM_MCW))[p * 64 + row];
            mf = fminf(mf, mv[p]);
        }
        float sf = 0.f;
        #pragma unroll
        for (int p = 0; p < 32; p++)
            sf += ((float*)(smem + SM_PSW))[p * 64 + row] * __expf((mf - mv[p]) * 20.f);
        const float inv = 1.0f / sf;
        #pragma unroll
        for (int p = 0; p < 32; p++) {
            float f = __expf((mf - mv[p]) * 20.f) * inv;
            float thr = __expf((mv[p] - mf - MARGIN) * 20.f) * 0.995f;
            ((uint32_t*)(smem + SM_PSW))[p * 64 + row] = pack_bf2(f, thr);
        }
    }
    __syncthreads();

    // colsum + candidate scan over smem exp buffer
    {
        const int piece = (tid >> 5) * 4 + ((tid >> 3) & 3);
        const uint32_t* fthr = (const uint32_t*)(smem + SM_PSW) + piece * 64;
        int2* cand = (int2*)(smem + SM_B);
        int* cnt = (int*)(smem + SM_CNT);
        int* rowcnt = (int*)(smem + SM_RC);
        int* rowfirst = (int*)(smem + SM_RF);
        float cs0 = 0.f, cs1 = 0.f, cs2 = 0.f, cs3 = 0.f;
        for (int row = 0; row < 64; row++) {
            uint2 v = *(uint2*)(smem + SM_EXP + row * 2048 +
                                (uint32_t)((tid * 8) ^ ((row & 7) << 4)));
            float e0 = bf_lo(v.x), e1 = bf_hi(v.x);
            float e2 = bf_lo(v.y), e3 = bf_hi(v.y);
            uint32_t pk = fthr[row];
            float f = bf_lo(pk), thr = bf_hi(pk);
            cs0 = __fmaf_rn(e0, f, cs0);
            cs1 = __fmaf_rn(e1, f, cs1);
            cs2 = __fmaf_rn(e2, f, cs2);
            cs3 = __fmaf_rn(e3, f, cs3);
            bool h0 = e0 >= thr, h1 = e1 >= thr, h2 = e2 >= thr, h3 = e3 >= thr;
            if (__ballot_sync(0xffffffffu, h0 | h1 | h2 | h3)) {
                #pragma unroll
                for (int j = 0; j < 4; j++) {
                    bool h = (j == 0) ? h0 : (j == 1) ? h1 : (j == 2) ? h2 : h3;
                    if (h) {
                        int code = tid * 4 + j;
                        int rc = atomicAdd(&rowcnt[row], 1);
                        if (rc == 0) rowfirst[row] = code;
                        int p = atomicAdd(cnt, 1);
                        if (p < BLK_CAND) cand[p] = make_int2(row, code);
                    }
                }
            }
        }
        atomicAdd(&g_colsum[tid * 4 + 0], cs0);
        atomicAdd(&g_colsum[tid * 4 + 1], cs1);
        atomicAdd(&g_colsum[tid * 4 + 2], cs2);
        atomicAdd(&g_colsum[tid * 4 + 3], cs3);
        __syncthreads();

        // single-candidate rows: index decided, no exact recompute needed
        if (tid < 64 && rowcnt[tid] == 1)
            g_key[m0 + tid] = (unsigned long long)(unsigned)rowfirst[tid];

        // multi-candidate rows: flush for exact resolve
        int n = *cnt; if (n > BLK_CAND) n = BLK_CAND;
        for (int i = tid; i < n; i += 256) {
            int2 e = cand[i];
            if (rowcnt[e.x] >= 2) {
                int p = atomicAdd(&g_cand_count, 1);
                if (p < CAND_CAP) {
                    g_cand_row[p] = m0 + e.x;
                    g_cand_code[p] = e.y;
                }
            }
        }
    }
}

// ---------------- kernel 3: exact recompute of candidates --------------------
// Strict ascending-k FMA chain; loads double-buffered through NAMED float4
// registers (16 loads in flight), fully static control flow.
#define FMA4(A, B) do { \
    acc = __fmaf_rn(A.x, B.x, acc); acc = __fmaf_rn(A.y, B.y, acc); \
    acc = __fmaf_rn(A.z, B.z, acc); acc = __fmaf_rn(A.w, B.w, acc); } while (0)
#define BLK_A(J) do { \
    FMA4(pa0, qa0); FMA4(pa1, qa1); FMA4(pa2, qa2); FMA4(pa3, qa3); \
    if ((J) + 8 < 64) { \
        pa0 = z4[(J) + 8]; qa0 = e4[(J) + 8]; pa1 = z4[(J) + 9]; qa1 = e4[(J) + 9]; \
        pa2 = z4[(J) + 10]; qa2 = e4[(J) + 10]; pa3 = z4[(J) + 11]; qa3 = e4[(J) + 11]; } \
    } while (0)
#define BLK_B(J) do { \
    FMA4(pb0, qb0); FMA4(pb1, qb1); FMA4(pb2, qb2); FMA4(pb3, qb3); \
    if ((J) + 8 < 64) { \
        pb0 = z4[(J) + 8]; qb0 = e4[(J) + 8]; pb1 = z4[(J) + 9]; qb1 = e4[(J) + 9]; \
        pb2 = z4[(J) + 10]; qb2 = e4[(J) + 10]; pb3 = z4[(J) + 11]; qb3 = e4[(J) + 11]; } \
    } while (0)

__global__ __launch_bounds__(256) void resolve_kernel(const float* __restrict__ Z,
                                                      const float* __restrict__ E) {
    int count = g_cand_count;
    if (count > CAND_CAP) count = CAND_CAP;
    for (int i = blockIdx.x * blockDim.x + threadIdx.x; i < count;
         i += gridDim.x * blockDim.x) {
        int row = g_cand_row[i];
        int code = g_cand_code[i];
        const float4* z4 = (const float4*)(Z + (size_t)row * DIM);
        const float4* e4 = (const float4*)(E + (size_t)code * DIM);
        float4 pa0 = z4[0], qa0 = e4[0], pa1 = z4[1], qa1 = e4[1];
        float4 pa2 = z4[2], qa2 = e4[2], pa3 = z4[3], qa3 = e4[3];
        float4 pb0 = z4[4], qb0 = e4[4], pb1 = z4[5], qb1 = e4[5];
        float4 pb2 = z4[6], qb2 = e4[6], pb3 = z4[7], qb3 = e4[7];
        float acc = 0.f;
        BLK_A(0);  BLK_B(4);  BLK_A(8);  BLK_B(12);
        BLK_A(16); BLK_B(20); BLK_A(24); BLK_B(28);
        BLK_A(32); BLK_B(36); BLK_A(40); BLK_B(44);
        BLK_A(48); BLK_B(52); BLK_A(56); BLK_B(60);
        float t1 = __fadd_rn(g_sz[row], g_se[code]);
        float dd = __fadd_rn(t1, -(2.0f * acc));
        unsigned long long key =
            ((unsigned long long)__float_as_uint(dd) << 32) | (unsigned)code;
        atomicMin(&g_key[row], key);
    }
}

// ---------------- kernel 4: gather quantized, straight-through, loss ---------
__global__ __launch_bounds__(256) void gather_loss_kernel(
    const float* __restrict__ Z, const float* __restrict__ E,
    float* __restrict__ out_q, float* __restrict__ out_idx_f) {
    const int row = blockIdx.x;
    const int t = threadIdx.x;
    const int idx = (int)(g_key[row] & 0xFFFFFFFFu);
    float e  = E[(size_t)idx * DIM + t];
    float zv = Z[(size_t)row * DIM + t];
    float diff = __fadd_rn(e, -zv);
    out_q[(size_t)row * DIM + t] = __fadd_rn(zv, diff);
    float sq = diff * diff;
    if (t == 0) out_idx_f[row] = (float)idx;

    __shared__ float red[8];
    #pragma unroll
    for (int o = 16; o; o >>= 1) sq += __shfl_xor_sync(0xffffffffu, sq, o);
    if ((t & 31) == 0) red[t >> 5] = sq;
    __syncthreads();
    if (t < 8) {
        float x = red[t];
        #pragma unroll
        for (int o = 4; o; o >>= 1) x += __shfl_xor_sync(0xffu, x, o);
        if (t == 0) atomicAdd(&g_loss, x);
    }
}

// ---------------- kernel 5: finalize ------------------------------------------
__global__ void finalize_kernel(float* __restrict__ out_loss,
                                float* __restrict__ out_avg) {
    int k = blockIdx.x * blockDim.x + threadIdx.x;
    if (k < NCODES) out_avg[k] = g_colsum[k] * (1.0f / (float)NROWS);
    if (k == 0) {
        float mse = g_loss * (1.0f / (float)((size_t)NROWS * DIM));
        out_loss[0] = __fadd_rn(mse, 0.25f * mse);
    }
}

// -----------------------------------------------------------------------------
extern "C" void kernel_launch(void* const* d_in, const int* in_sizes, int n_in,
                              void* d_out, int out_size) {
    const float* Z = (const float*)d_in[0];
    const float* E = (const float*)d_in[1];
    if (n_in >= 2 && in_sizes[0] == NCODES * DIM && in_sizes[1] == NROWS * DIM) {
        E = (const float*)d_in[0];
        Z = (const float*)d_in[1];
    }

    float* out       = (float*)d_out;
    float* out_q     = out;                              // 8388608
    float* out_loss  = out + (size_t)NROWS * DIM;        // 1
    float* out_idx_f = out_loss + 1;                     // 32768
    float* out_avg   = out_idx_f + NROWS;                // 1024

    cudaFuncSetAttribute(fused_kernel,
                         cudaFuncAttributeMaxDynamicSharedMemorySize, SM_TOT);

    prep_se_kernel<<<(NCODES + 255) / 256, 256>>>(E);
    prep_sz_kernel<<<NROWS / 256, 256>>>(Z);
    fused_kernel<<<NROWS / 64, 256, SM_TOT>>>();
    resolve_kernel<<<512, 256>>>(Z, E);
    gather_loss_kernel<<<NROWS, 256>>>(Z, E, out_q, out_idx_f);
    finalize_kernel<<<(NCODES + 255) / 256, 256>>>(out_loss, out_avg);
}